// round 6
// baseline (speedup 1.0000x reference)
#include <cuda_runtime.h>
#include <cuda_fp16.h>
#include <math.h>
#include <stdint.h>

#define BB 2
#define CC 64
#define HH 128
#define WW 160
#define DD 16
#define VV 4
#define NV 9
#define HWP (HH*WW)

// ---------------- scratch (static device memory; no allocation) ----------------
__device__ __align__(16) __half g_srcT[(size_t)VV*BB*HWP*CC]; // fp16 [v*B+b][hw][c]
__device__ __align__(16) __half g_refT[(size_t)BB*HWP*CC];    // fp16 [b][hw][c]
__device__ float g_proj[VV*BB*12];
__device__ __align__(16) float g_s[(size_t)BB*HWP*DD];        // s channels-last [b][hw][d]

#define BNS 0.9999950000374997f

// ---------------- K0: transpose [C,HW] -> [HW,C]; all -> fp16 ----------------
__global__ void k_transpose(const float* __restrict__ ref, const float* __restrict__ src) {
    __shared__ float tile[64][65];
    int img = blockIdx.y;          // 0..7 = src v*B+b, 8..9 = ref b
    int hw0 = blockIdx.x * 64;
    const float* in = (img < VV*BB) ? (src + (size_t)img*CC*HWP)
                                    : (ref + (size_t)(img - VV*BB)*CC*HWP);
    for (int k = threadIdx.x; k < 64*64; k += blockDim.x) {
        int c = k >> 6, hwl = k & 63;
        tile[hwl][c] = in[(size_t)c*HWP + hw0 + hwl];
    }
    __syncthreads();
    __half2* out = (img < VV*BB)
        ? (__half2*)(g_srcT + (size_t)img*HWP*CC)
        : (__half2*)(g_refT + (size_t)(img - VV*BB)*HWP*CC);
    for (int k = threadIdx.x; k < 64*32; k += blockDim.x) {
        int hwl = k >> 5, cp = k & 31;
        out[(size_t)(hw0+hwl)*(CC/2) + cp] =
            __floats2half2_rn(tile[hwl][2*cp], tile[hwl][2*cp+1]);
    }
}

// ---------------- K1: proj = src_proj @ inv(ref_proj) ----------------
__global__ void k_proj(const float* __restrict__ ref_proj, const float* __restrict__ src_projs) {
    int t = threadIdx.x;
    if (t >= VV*BB) return;
    int v = t / BB, b = t % BB;
    float a[4][4], inv[4][4];
    #pragma unroll
    for (int i = 0; i < 4; i++)
        #pragma unroll
        for (int j = 0; j < 4; j++) {
            a[i][j] = ref_proj[b*16 + i*4 + j];
            inv[i][j] = (i == j) ? 1.f : 0.f;
        }
    for (int col = 0; col < 4; col++) {
        int piv = col; float best = fabsf(a[col][col]);
        for (int r = col+1; r < 4; r++) { float av = fabsf(a[r][col]); if (av > best) { best = av; piv = r; } }
        if (piv != col) {
            for (int j = 0; j < 4; j++) {
                float tm = a[col][j]; a[col][j] = a[piv][j]; a[piv][j] = tm;
                tm = inv[col][j]; inv[col][j] = inv[piv][j]; inv[piv][j] = tm;
            }
        }
        float dsc = 1.f / a[col][col];
        for (int j = 0; j < 4; j++) { a[col][j] *= dsc; inv[col][j] *= dsc; }
        for (int r = 0; r < 4; r++) {
            if (r == col) continue;
            float f = a[r][col];
            for (int j = 0; j < 4; j++) { a[r][j] -= f*a[col][j]; inv[r][j] -= f*inv[col][j]; }
        }
    }
    const float* s = src_projs + (size_t)(v*BB + b)*16;
    float* o = g_proj + (v*BB + b)*12;
    for (int i = 0; i < 3; i++)
        for (int j = 0; j < 4; j++) {
            float acc = 0.f;
            for (int k = 0; k < 4; k++) acc += s[i*4 + k] * inv[k][j];
            o[i*4 + j] = acc;
        }
}

// ---------------- fp16 packed MLP (8 -> 16 -> 8 -> 1) ----------------
__device__ __forceinline__ __half2 u2h(uint32_t u) { return *reinterpret_cast<__half2*>(&u); }

__device__ __forceinline__ float mlp8h(const uint32_t* __restrict__ swh, const float in8[8]) {
    __half2 ind[8];
    #pragma unroll
    for (int g = 0; g < 8; g++) ind[g] = __float2half2_rn(in8[g]);
    const uint4* W0 = (const uint4*)swh;
    const uint4* W1 = (const uint4*)(swh + 80);
    const __half2 zero = __float2half2_rn(0.f);
    __half2 h1[8];
    #pragma unroll
    for (int jp = 0; jp < 8; jp++) {
        uint4 wa = W0[jp*2], wb = W0[jp*2+1];
        __half2 acc = __hmul2(u2h(wa.x), ind[0]);
        acc = __hfma2(u2h(wa.y), ind[1], acc);
        acc = __hfma2(u2h(wa.z), ind[2], acc);
        acc = __hfma2(u2h(wa.w), ind[3], acc);
        acc = __hfma2(u2h(wb.x), ind[4], acc);
        acc = __hfma2(u2h(wb.y), ind[5], acc);
        acc = __hfma2(u2h(wb.z), ind[6], acc);
        acc = __hfma2(u2h(wb.w), ind[7], acc);
        acc = __hfma2(acc, u2h(swh[64 + jp]), u2h(swh[72 + jp]));
        h1[jp] = __hmax2(acc, zero);
    }
    __half2 hd[16];
    #pragma unroll
    for (int jp = 0; jp < 8; jp++) {
        hd[2*jp]   = __low2half2(h1[jp]);
        hd[2*jp+1] = __high2half2(h1[jp]);
    }
    __half2 oacc = zero;
    #pragma unroll
    for (int kp = 0; kp < 4; kp++) {
        uint4 w0v = W1[kp*4], w1v = W1[kp*4+1], w2v = W1[kp*4+2], w3v = W1[kp*4+3];
        __half2 acc = __hmul2(u2h(w0v.x), hd[0]);
        acc = __hfma2(u2h(w0v.y), hd[1], acc);
        acc = __hfma2(u2h(w0v.z), hd[2], acc);
        acc = __hfma2(u2h(w0v.w), hd[3], acc);
        acc = __hfma2(u2h(w1v.x), hd[4], acc);
        acc = __hfma2(u2h(w1v.y), hd[5], acc);
        acc = __hfma2(u2h(w1v.z), hd[6], acc);
        acc = __hfma2(u2h(w1v.w), hd[7], acc);
        acc = __hfma2(u2h(w2v.x), hd[8], acc);
        acc = __hfma2(u2h(w2v.y), hd[9], acc);
        acc = __hfma2(u2h(w2v.z), hd[10], acc);
        acc = __hfma2(u2h(w2v.w), hd[11], acc);
        acc = __hfma2(u2h(w3v.x), hd[12], acc);
        acc = __hfma2(u2h(w3v.y), hd[13], acc);
        acc = __hfma2(u2h(w3v.z), hd[14], acc);
        acc = __hfma2(u2h(w3v.w), hd[15], acc);
        acc = __hfma2(acc, u2h(swh[144 + kp]), u2h(swh[148 + kp]));
        acc = __hmax2(acc, zero);
        oacc = __hfma2(u2h(swh[152 + kp]), acc, oacc);
    }
    float2 of = __half22float2(oacc);
    return of.x + of.y + __uint_as_float(swh[156]);
}

// ---------------- K2: warp + group correlation + pixelwise net + similarity net ----------------
// block = 128 threads = 8 pixels × 16 lanes; lane = (dh, g): dh = lane>>3, g = lane&7.
// Lane owns depth d_own = lane for Phase A + MLP; Phase B: lane samples group g for depths dh*8+dl.
__global__ void __launch_bounds__(128)
k_main(const float* __restrict__ depth_sample,
       const float* __restrict__ pw_w0, const float* __restrict__ pw_g0, const float* __restrict__ pw_b0,
       const float* __restrict__ pw_w1, const float* __restrict__ pw_g1, const float* __restrict__ pw_b1,
       const float* __restrict__ pw_w2, const float* __restrict__ pw_c2b,
       const float* __restrict__ sn_w0, const float* __restrict__ sn_g0, const float* __restrict__ sn_b0,
       const float* __restrict__ sn_w1, const float* __restrict__ sn_g1, const float* __restrict__ sn_b1,
       const float* __restrict__ sn_w2, const float* __restrict__ sn_c2b,
       float* __restrict__ out_vw) {
    __shared__ __align__(16) uint32_t swh[2][160];
    __shared__ __align__(16) uint32_t scoord[8][16][8]; // [pix][d][4 idx + 4 w(half2dup)]
    __shared__ __align__(16) __half  simv[8][16][8];    // [pix][d][group]

    int tid = threadIdx.x;

    // pack fp16 MLP weights
    for (int i = tid; i < 320; i += 128) {
        int net = i / 160, j = i - net*160;
        const float* w0 = net ? sn_w0 : pw_w0;
        const float* g0 = net ? sn_g0 : pw_g0;
        const float* b0 = net ? sn_b0 : pw_b0;
        const float* w1 = net ? sn_w1 : pw_w1;
        const float* g1 = net ? sn_g1 : pw_g1;
        const float* b1 = net ? sn_b1 : pw_b1;
        const float* w2 = net ? sn_w2 : pw_w2;
        const float* cb = net ? sn_c2b : pw_c2b;
        uint32_t val;
        if (j < 64) {
            int jp = j >> 3, g = j & 7;
            __half2 h = __floats2half2_rn(w0[(2*jp)*8 + g], w0[(2*jp+1)*8 + g]);
            val = *reinterpret_cast<uint32_t*>(&h);
        } else if (j < 72) {
            int jp = j - 64;
            __half2 h = __floats2half2_rn(g0[2*jp]*BNS, g0[2*jp+1]*BNS);
            val = *reinterpret_cast<uint32_t*>(&h);
        } else if (j < 80) {
            int jp = j - 72;
            __half2 h = __floats2half2_rn(b0[2*jp], b0[2*jp+1]);
            val = *reinterpret_cast<uint32_t*>(&h);
        } else if (j < 144) {
            int idx = j - 80; int kp = idx >> 4, jj = idx & 15;
            __half2 h = __floats2half2_rn(w1[(2*kp)*16 + jj], w1[(2*kp+1)*16 + jj]);
            val = *reinterpret_cast<uint32_t*>(&h);
        } else if (j < 148) {
            int kp = j - 144;
            __half2 h = __floats2half2_rn(g1[2*kp]*BNS, g1[2*kp+1]*BNS);
            val = *reinterpret_cast<uint32_t*>(&h);
        } else if (j < 152) {
            int kp = j - 148;
            __half2 h = __floats2half2_rn(b1[2*kp], b1[2*kp+1]);
            val = *reinterpret_cast<uint32_t*>(&h);
        } else if (j < 156) {
            int kp = j - 152;
            __half2 h = __floats2half2_rn(w2[2*kp], w2[2*kp+1]);
            val = *reinterpret_cast<uint32_t*>(&h);
        } else {
            val = __float_as_uint(cb[0]);
        }
        swh[net][j] = val;
    }
    __syncthreads();

    int pix  = tid >> 4;         // 0..7 within block (2 pixels per warp)
    int lane = tid & 15;         // 0..15: owned depth
    int dh   = lane >> 3;        // depth-half for Phase B
    int g    = lane & 7;         // group for Phase B
    int p = blockIdx.x * 8 + pix;
    int b  = p / HWP;
    int hw = p - b * HWP;
    int h = hw / WW, w = hw - h * WW;
    float wf = (float)w, hf = (float)h;

    // ref features for group g (8 channels fp16 = one uint4)
    uint4 ru = __ldg((const uint4*)(g_refT + (size_t)p*CC) + g);
    __half2 rh0 = u2h(ru.x), rh1 = u2h(ru.y), rh2 = u2h(ru.z), rh3 = u2h(ru.w);

    // depth owned by this lane
    float myDep = __ldg(depth_sample + (size_t)b*DD*HWP + (size_t)lane*HWP + hw);

    float acc[8];
    #pragma unroll
    for (int k = 0; k < 8; k++) acc[k] = 0.f;
    float wsum = 0.f;

    for (int v = 0; v < VV; v++) {
        const float* M = g_proj + (v*BB + b)*12;
        float rx = M[0]*wf + M[1]*hf + M[2];
        float ry = M[4]*wf + M[5]*hf + M[6];
        float rz = M[8]*wf + M[9]*hf + M[10];
        float t0 = M[3], t1 = M[7], t2 = M[11];
        const __half* srcB = g_srcT + (size_t)(v*BB + b)*HWP*CC;

        // ---- Phase A: coords for owned depth ----
        {
            float px = rx*myDep + t0, py = ry*myDep + t1, pz = rz*myDep + t2;
            if (pz <= 0.001f) { px = (float)WW; py = (float)HH; pz = 1.f; }
            float ix = __fdividef(px, pz);
            float iy = __fdividef(py, pz);
            float x0f = floorf(ix), y0f = floorf(iy);
            float fx = ix - x0f, fy = iy - y0f;
            int x0 = (int)x0f, y0 = (int)y0f;
            int x1 = x0 + 1, y1 = y0 + 1;
            bool vx0 = (x0 >= 0) & (x0 < WW);
            bool vx1 = (x1 >= 0) & (x1 < WW);
            bool vy0 = (y0 >= 0) & (y0 < HH);
            bool vy1 = (y1 >= 0) & (y1 < HH);
            float w00 = (1.f-fx)*(1.f-fy) * (float)(vx0 && vy0);
            float w01 = fx*(1.f-fy)       * (float)(vx1 && vy0);
            float w10 = (1.f-fx)*fy       * (float)(vx0 && vy1);
            float w11 = fx*fy             * (float)(vx1 && vy1);
            int xc0 = min(max(x0, 0), WW-1), xc1 = min(max(x1, 0), WW-1);
            int yc0 = min(max(y0, 0), HH-1), yc1 = min(max(y1, 0), HH-1);
            int r0 = yc0*WW, r1 = yc1*WW;
            uint32_t* sc = scoord[pix][lane];
            sc[0] = (uint32_t)(r0 + xc0);
            sc[1] = (uint32_t)(r0 + xc1);
            sc[2] = (uint32_t)(r1 + xc0);
            sc[3] = (uint32_t)(r1 + xc1);
            __half2 h00 = __float2half2_rn(w00);
            __half2 h01 = __float2half2_rn(w01);
            __half2 h10 = __float2half2_rn(w10);
            __half2 h11 = __float2half2_rn(w11);
            sc[4] = *reinterpret_cast<uint32_t*>(&h00);
            sc[5] = *reinterpret_cast<uint32_t*>(&h01);
            sc[6] = *reinterpret_cast<uint32_t*>(&h10);
            sc[7] = *reinterpret_cast<uint32_t*>(&h11);
        }
        __syncwarp();

        // ---- Phase B: 8 depths per lane (lane = dh half, group g) ----
        #pragma unroll
        for (int dl = 0; dl < 8; dl++) {
            int d = dh*8 + dl;
            uint4 ci = *(const uint4*)&scoord[pix][d][0];
            uint4 cw = *(const uint4*)&scoord[pix][d][4];
            uint4 u00 = __ldg((const uint4*)(srcB + (size_t)ci.x*CC) + g);
            uint4 u01 = __ldg((const uint4*)(srcB + (size_t)ci.y*CC) + g);
            uint4 u10 = __ldg((const uint4*)(srcB + (size_t)ci.z*CC) + g);
            uint4 u11 = __ldg((const uint4*)(srcB + (size_t)ci.w*CC) + g);
            __half2 w00 = u2h(cw.x), w01 = u2h(cw.y), w10 = u2h(cw.z), w11 = u2h(cw.w);
            __half2 m0 = __hmul2(u2h(u00.x), w00);
            __half2 m1 = __hmul2(u2h(u00.y), w00);
            __half2 m2 = __hmul2(u2h(u00.z), w00);
            __half2 m3 = __hmul2(u2h(u00.w), w00);
            m0 = __hfma2(u2h(u01.x), w01, m0);
            m1 = __hfma2(u2h(u01.y), w01, m1);
            m2 = __hfma2(u2h(u01.z), w01, m2);
            m3 = __hfma2(u2h(u01.w), w01, m3);
            m0 = __hfma2(u2h(u10.x), w10, m0);
            m1 = __hfma2(u2h(u10.y), w10, m1);
            m2 = __hfma2(u2h(u10.z), w10, m2);
            m3 = __hfma2(u2h(u10.w), w10, m3);
            m0 = __hfma2(u2h(u11.x), w11, m0);
            m1 = __hfma2(u2h(u11.y), w11, m1);
            m2 = __hfma2(u2h(u11.z), w11, m2);
            m3 = __hfma2(u2h(u11.w), w11, m3);
            __half2 da = __hmul2(m0, rh0);
            da = __hfma2(m1, rh1, da);
            da = __hfma2(m2, rh2, da);
            da = __hfma2(m3, rh3, da);
            float2 df = __half22float2(da);
            simv[pix][d][g] = __float2half_rn((df.x + df.y) * 0.125f);
        }
        __syncwarp();

        // ---- pixelwise net: lane owns depth = lane ----
        uint4 sv = *(const uint4*)&simv[pix][lane][0];
        float in8[8];
        {
            float2 a0 = __half22float2(u2h(sv.x));
            float2 a1 = __half22float2(u2h(sv.y));
            float2 a2 = __half22float2(u2h(sv.z));
            float2 a3 = __half22float2(u2h(sv.w));
            in8[0]=a0.x; in8[1]=a0.y; in8[2]=a1.x; in8[3]=a1.y;
            in8[4]=a2.x; in8[5]=a2.y; in8[6]=a3.x; in8[7]=a3.y;
        }
        float o = mlp8h(swh[0], in8);
        float vwv = __frcp_rn(1.f + __expf(-o));
        #pragma unroll
        for (int k = 8; k >= 1; k >>= 1)
            vwv = fmaxf(vwv, __shfl_xor_sync(0xffffffffu, vwv, k, 16));
        #pragma unroll
        for (int k = 0; k < 8; k++) acc[k] += in8[k]*vwv;
        wsum += vwv;
        if (lane == 0) out_vw[((size_t)b*VV + v)*HWP + hw] = vwv;
        __syncwarp();
    }

    float rws = 1.f / wsum;
    float in8[8];
    #pragma unroll
    for (int k = 0; k < 8; k++) in8[k] = acc[k]*rws;
    float sval = mlp8h(swh[1], in8);
    g_s[(size_t)p*DD + lane] = sval;
}

// ---------------- K3: grid-sample + NN aggregation + softmax + depth ----------------
__global__ void __launch_bounds__(128)
k_final(const float* __restrict__ grid, const float* __restrict__ weight,
        const float* __restrict__ depth_sample, const int* __restrict__ is_inverse,
        float* __restrict__ out_depth, float* __restrict__ out_score) {
    int t = blockIdx.x * blockDim.x + threadIdx.x;
    int p = t >> 2;
    int q = t & 3;
    if (p >= BB*HWP) return;
    int b  = p / HWP;
    int hw = p - b * HWP;
    int h = hw / WW, w = hw - h * WW;

    float agg[4] = {0.f, 0.f, 0.f, 0.f};

    const float* wbase = weight + ((size_t)b*DD*NV)*HWP + hw + (size_t)(q*4)*NV*HWP;
    #pragma unroll
    for (int n = 0; n < NV; n++) {
        const float* gp = grid + (((size_t)b*NV*HH + n*HH + h)*WW + w)*2;
        float gx = __ldg(gp), gy = __ldg(gp + 1);
        float ix = ((gx + 1.f)*WW - 1.f) * 0.5f;
        float iy = ((gy + 1.f)*HH - 1.f) * 0.5f;
        float x0f = floorf(ix), y0f = floorf(iy);
        float fx = ix - x0f, fy = iy - y0f;
        int x0 = (int)x0f, y0 = (int)y0f;
        int xc0 = min(max(x0, 0), WW-1), xc1 = min(max(x0+1, 0), WW-1);
        int yc0 = min(max(y0, 0), HH-1), yc1 = min(max(y0+1, 0), HH-1);
        float w00 = (1.f-fx)*(1.f-fy), w01 = fx*(1.f-fy);
        float w10 = (1.f-fx)*fy,       w11 = fx*fy;
        float4 a00 = __ldg((const float4*)(g_s + ((size_t)b*HWP + yc0*WW + xc0)*DD) + q);
        float4 a01 = __ldg((const float4*)(g_s + ((size_t)b*HWP + yc0*WW + xc1)*DD) + q);
        float4 a10 = __ldg((const float4*)(g_s + ((size_t)b*HWP + yc1*WW + xc0)*DD) + q);
        float4 a11 = __ldg((const float4*)(g_s + ((size_t)b*HWP + yc1*WW + xc1)*DD) + q);
        float bx = w00*a00.x + w01*a01.x + w10*a10.x + w11*a11.x;
        float by = w00*a00.y + w01*a01.y + w10*a10.y + w11*a11.y;
        float bz = w00*a00.z + w01*a01.z + w10*a10.z + w11*a11.z;
        float bw = w00*a00.w + w01*a01.w + w10*a10.w + w11*a11.w;
        const float* wb = wbase + (size_t)n*HWP;
        agg[0] += __ldg(wb)                      * bx;
        agg[1] += __ldg(wb + (size_t)1*NV*HWP)   * by;
        agg[2] += __ldg(wb + (size_t)2*NV*HWP)   * bz;
        agg[3] += __ldg(wb + (size_t)3*NV*HWP)   * bw;
    }

    float m = fmaxf(fmaxf(agg[0], agg[1]), fmaxf(agg[2], agg[3]));
    m = fmaxf(m, __shfl_xor_sync(0xffffffffu, m, 1, 4));
    m = fmaxf(m, __shfl_xor_sync(0xffffffffu, m, 2, 4));
    float e[4]; float sum = 0.f;
    #pragma unroll
    for (int j = 0; j < 4; j++) { e[j] = __expf(agg[j] - m); sum += e[j]; }
    sum += __shfl_xor_sync(0xffffffffu, sum, 1, 4);
    sum += __shfl_xor_sync(0xffffffffu, sum, 2, 4);
    float rs = 1.f / sum;

    const float* dsB = depth_sample + (size_t)b*DD*HWP + hw;
    float dep = 0.f;
    int inv = *is_inverse;
    #pragma unroll
    for (int j = 0; j < 4; j++) {
        float sc = e[j] * rs;
        int d = q*4 + j;
        out_score[((size_t)b*DD + d)*HWP + hw] = sc;
        if (inv) dep += (float)d * sc;
        else     dep += __ldg(dsB + (size_t)d*HWP) * sc;
    }
    dep += __shfl_xor_sync(0xffffffffu, dep, 1, 4);
    dep += __shfl_xor_sync(0xffffffffu, dep, 2, 4);
    if (q == 0) {
        if (inv) {
            float invmin = 1.f / __ldg(dsB + (size_t)(DD-1)*HWP);
            float invmax = 1.f / __ldg(dsB);
            dep = 1.f / (invmax + dep * (1.f/(float)(DD-1)) * (invmin - invmax));
        }
        out_depth[p] = dep;
    }
}

// ---------------- launch ----------------
extern "C" void kernel_launch(void* const* d_in, const int* in_sizes, int n_in,
                              void* d_out, int out_size) {
    const float* ref_feature  = (const float*)d_in[0];
    const float* src_features = (const float*)d_in[1];
    const float* ref_proj     = (const float*)d_in[2];
    const float* src_projs    = (const float*)d_in[3];
    const float* depth_sample = (const float*)d_in[4];
    const float* grid         = (const float*)d_in[5];
    const float* weight       = (const float*)d_in[6];
    const float* pw_w0  = (const float*)d_in[7];
    const float* pw_g0  = (const float*)d_in[8];
    const float* pw_b0  = (const float*)d_in[9];
    const float* pw_w1  = (const float*)d_in[10];
    const float* pw_g1  = (const float*)d_in[11];
    const float* pw_b1  = (const float*)d_in[12];
    const float* pw_w2  = (const float*)d_in[13];
    const float* pw_c2b = (const float*)d_in[14];
    const float* sn_w0  = (const float*)d_in[15];
    const float* sn_g0  = (const float*)d_in[16];
    const float* sn_b0  = (const float*)d_in[17];
    const float* sn_w1  = (const float*)d_in[18];
    const float* sn_g1  = (const float*)d_in[19];
    const float* sn_b1  = (const float*)d_in[20];
    const float* sn_w2  = (const float*)d_in[21];
    const float* sn_c2b = (const float*)d_in[22];
    const int*   is_inv = (const int*)d_in[23];

    float* out       = (float*)d_out;
    float* out_depth = out;
    float* out_score = out + (size_t)BB*HWP;
    float* out_vw    = out + (size_t)BB*HWP + (size_t)BB*DD*HWP;

    k_transpose<<<dim3(HWP/64, VV*BB + BB), 256>>>(ref_feature, src_features);
    k_proj<<<1, 32>>>(ref_proj, src_projs);
    k_main<<<BB*HWP/8, 128>>>(depth_sample,
                              pw_w0, pw_g0, pw_b0, pw_w1, pw_g1, pw_b1, pw_w2, pw_c2b,
                              sn_w0, sn_g0, sn_b0, sn_w1, sn_g1, sn_b1, sn_w2, sn_c2b,
                              out_vw);
    k_final<<<(BB*HWP*4 + 127)/128, 128>>>(grid, weight, depth_sample, is_inv,
                                           out_depth, out_score);
}

// round 7
// speedup vs baseline: 1.1049x; 1.1049x over previous
#include <cuda_runtime.h>
#include <cuda_fp16.h>
#include <math.h>
#include <stdint.h>

#define BB 2
#define CC 64
#define HH 128
#define WW 160
#define DD 16
#define VV 4
#define NV 9
#define HWP (HH*WW)

// ---------------- scratch (static device memory; no allocation) ----------------
__device__ __align__(16) __half g_srcT[(size_t)VV*BB*HWP*CC]; // fp16 [v*B+b][hw][c]
__device__ __align__(16) __half g_refT[(size_t)BB*HWP*CC];    // fp16 [b][hw][c]
__device__ float g_proj[VV*BB*12];
__device__ __align__(16) float g_s[(size_t)BB*HWP*DD];        // s channels-last [b][hw][d]

#define BNS 0.9999950000374997f

// ---------------- K0: transpose [C,HW] -> [HW,C]; all -> fp16 ----------------
__global__ void k_transpose(const float* __restrict__ ref, const float* __restrict__ src) {
    __shared__ float tile[64][65];
    int img = blockIdx.y;          // 0..7 = src v*B+b, 8..9 = ref b
    int hw0 = blockIdx.x * 64;
    const float* in = (img < VV*BB) ? (src + (size_t)img*CC*HWP)
                                    : (ref + (size_t)(img - VV*BB)*CC*HWP);
    for (int k = threadIdx.x; k < 64*64; k += blockDim.x) {
        int c = k >> 6, hwl = k & 63;
        tile[hwl][c] = in[(size_t)c*HWP + hw0 + hwl];
    }
    __syncthreads();
    __half2* out = (img < VV*BB)
        ? (__half2*)(g_srcT + (size_t)img*HWP*CC)
        : (__half2*)(g_refT + (size_t)(img - VV*BB)*HWP*CC);
    for (int k = threadIdx.x; k < 64*32; k += blockDim.x) {
        int hwl = k >> 5, cp = k & 31;
        out[(size_t)(hw0+hwl)*(CC/2) + cp] =
            __floats2half2_rn(tile[hwl][2*cp], tile[hwl][2*cp+1]);
    }
}

// ---------------- K1: proj = src_proj @ inv(ref_proj) ----------------
__global__ void k_proj(const float* __restrict__ ref_proj, const float* __restrict__ src_projs) {
    int t = threadIdx.x;
    if (t >= VV*BB) return;
    int v = t / BB, b = t % BB;
    float a[4][4], inv[4][4];
    #pragma unroll
    for (int i = 0; i < 4; i++)
        #pragma unroll
        for (int j = 0; j < 4; j++) {
            a[i][j] = ref_proj[b*16 + i*4 + j];
            inv[i][j] = (i == j) ? 1.f : 0.f;
        }
    for (int col = 0; col < 4; col++) {
        int piv = col; float best = fabsf(a[col][col]);
        for (int r = col+1; r < 4; r++) { float av = fabsf(a[r][col]); if (av > best) { best = av; piv = r; } }
        if (piv != col) {
            for (int j = 0; j < 4; j++) {
                float tm = a[col][j]; a[col][j] = a[piv][j]; a[piv][j] = tm;
                tm = inv[col][j]; inv[col][j] = inv[piv][j]; inv[piv][j] = tm;
            }
        }
        float dsc = 1.f / a[col][col];
        for (int j = 0; j < 4; j++) { a[col][j] *= dsc; inv[col][j] *= dsc; }
        for (int r = 0; r < 4; r++) {
            if (r == col) continue;
            float f = a[r][col];
            for (int j = 0; j < 4; j++) { a[r][j] -= f*a[col][j]; inv[r][j] -= f*inv[col][j]; }
        }
    }
    const float* s = src_projs + (size_t)(v*BB + b)*16;
    float* o = g_proj + (v*BB + b)*12;
    for (int i = 0; i < 3; i++)
        for (int j = 0; j < 4; j++) {
            float acc = 0.f;
            for (int k = 0; k < 4; k++) acc += s[i*4 + k] * inv[k][j];
            o[i*4 + j] = acc;
        }
}

// ---------------- fp16 packed MLP (8 -> 16 -> 8 -> 1) ----------------
__device__ __forceinline__ __half2 u2h(uint32_t u) { return *reinterpret_cast<__half2*>(&u); }

__device__ __forceinline__ float mlp8h(const uint32_t* __restrict__ swh, const float in8[8]) {
    __half2 ind[8];
    #pragma unroll
    for (int g = 0; g < 8; g++) ind[g] = __float2half2_rn(in8[g]);
    const uint4* W0 = (const uint4*)swh;
    const uint4* W1 = (const uint4*)(swh + 80);
    const __half2 zero = __float2half2_rn(0.f);
    __half2 h1[8];
    #pragma unroll
    for (int jp = 0; jp < 8; jp++) {
        uint4 wa = W0[jp*2], wb = W0[jp*2+1];
        __half2 acc = __hmul2(u2h(wa.x), ind[0]);
        acc = __hfma2(u2h(wa.y), ind[1], acc);
        acc = __hfma2(u2h(wa.z), ind[2], acc);
        acc = __hfma2(u2h(wa.w), ind[3], acc);
        acc = __hfma2(u2h(wb.x), ind[4], acc);
        acc = __hfma2(u2h(wb.y), ind[5], acc);
        acc = __hfma2(u2h(wb.z), ind[6], acc);
        acc = __hfma2(u2h(wb.w), ind[7], acc);
        acc = __hfma2(acc, u2h(swh[64 + jp]), u2h(swh[72 + jp]));
        h1[jp] = __hmax2(acc, zero);
    }
    __half2 hd[16];
    #pragma unroll
    for (int jp = 0; jp < 8; jp++) {
        hd[2*jp]   = __low2half2(h1[jp]);
        hd[2*jp+1] = __high2half2(h1[jp]);
    }
    __half2 oacc = zero;
    #pragma unroll
    for (int kp = 0; kp < 4; kp++) {
        uint4 w0v = W1[kp*4], w1v = W1[kp*4+1], w2v = W1[kp*4+2], w3v = W1[kp*4+3];
        __half2 acc = __hmul2(u2h(w0v.x), hd[0]);
        acc = __hfma2(u2h(w0v.y), hd[1], acc);
        acc = __hfma2(u2h(w0v.z), hd[2], acc);
        acc = __hfma2(u2h(w0v.w), hd[3], acc);
        acc = __hfma2(u2h(w1v.x), hd[4], acc);
        acc = __hfma2(u2h(w1v.y), hd[5], acc);
        acc = __hfma2(u2h(w1v.z), hd[6], acc);
        acc = __hfma2(u2h(w1v.w), hd[7], acc);
        acc = __hfma2(u2h(w2v.x), hd[8], acc);
        acc = __hfma2(u2h(w2v.y), hd[9], acc);
        acc = __hfma2(u2h(w2v.z), hd[10], acc);
        acc = __hfma2(u2h(w2v.w), hd[11], acc);
        acc = __hfma2(u2h(w3v.x), hd[12], acc);
        acc = __hfma2(u2h(w3v.y), hd[13], acc);
        acc = __hfma2(u2h(w3v.z), hd[14], acc);
        acc = __hfma2(u2h(w3v.w), hd[15], acc);
        acc = __hfma2(acc, u2h(swh[144 + kp]), u2h(swh[148 + kp]));
        acc = __hmax2(acc, zero);
        oacc = __hfma2(u2h(swh[152 + kp]), acc, oacc);
    }
    float2 of = __half22float2(oacc);
    return of.x + of.y + __uint_as_float(swh[156]);
}

// ---------------- K2: warp + group correlation + pixelwise net + similarity net ----------------
// block = 128 threads = 8 pixels × 16 lanes; lane = (dh, g).
// Conflict-free shared layouts: scoord rows stride 9 words, simv rows stride 5 words.
__global__ void __launch_bounds__(128)
k_main(const float* __restrict__ depth_sample,
       const float* __restrict__ pw_w0, const float* __restrict__ pw_g0, const float* __restrict__ pw_b0,
       const float* __restrict__ pw_w1, const float* __restrict__ pw_g1, const float* __restrict__ pw_b1,
       const float* __restrict__ pw_w2, const float* __restrict__ pw_c2b,
       const float* __restrict__ sn_w0, const float* __restrict__ sn_g0, const float* __restrict__ sn_b0,
       const float* __restrict__ sn_w1, const float* __restrict__ sn_g1, const float* __restrict__ sn_b1,
       const float* __restrict__ sn_w2, const float* __restrict__ sn_c2b,
       float* __restrict__ out_vw) {
    __shared__ __align__(16) uint32_t swh[2][160];
    __shared__ uint32_t scoord[8][16][9]; // [pix][d][4 idx + 4 w + pad]; stride 9 (coprime w/ 32)
    __shared__ uint32_t simh [8][16][5];  // [pix][d][4 half2 + pad]; stride 5 (coprime w/ 32)

    int tid = threadIdx.x;

    // pack fp16 MLP weights
    for (int i = tid; i < 320; i += 128) {
        int net = i / 160, j = i - net*160;
        const float* w0 = net ? sn_w0 : pw_w0;
        const float* g0 = net ? sn_g0 : pw_g0;
        const float* b0 = net ? sn_b0 : pw_b0;
        const float* w1 = net ? sn_w1 : pw_w1;
        const float* g1 = net ? sn_g1 : pw_g1;
        const float* b1 = net ? sn_b1 : pw_b1;
        const float* w2 = net ? sn_w2 : pw_w2;
        const float* cb = net ? sn_c2b : pw_c2b;
        uint32_t val;
        if (j < 64) {
            int jp = j >> 3, g = j & 7;
            __half2 h = __floats2half2_rn(w0[(2*jp)*8 + g], w0[(2*jp+1)*8 + g]);
            val = *reinterpret_cast<uint32_t*>(&h);
        } else if (j < 72) {
            int jp = j - 64;
            __half2 h = __floats2half2_rn(g0[2*jp]*BNS, g0[2*jp+1]*BNS);
            val = *reinterpret_cast<uint32_t*>(&h);
        } else if (j < 80) {
            int jp = j - 72;
            __half2 h = __floats2half2_rn(b0[2*jp], b0[2*jp+1]);
            val = *reinterpret_cast<uint32_t*>(&h);
        } else if (j < 144) {
            int idx = j - 80; int kp = idx >> 4, jj = idx & 15;
            __half2 h = __floats2half2_rn(w1[(2*kp)*16 + jj], w1[(2*kp+1)*16 + jj]);
            val = *reinterpret_cast<uint32_t*>(&h);
        } else if (j < 148) {
            int kp = j - 144;
            __half2 h = __floats2half2_rn(g1[2*kp]*BNS, g1[2*kp+1]*BNS);
            val = *reinterpret_cast<uint32_t*>(&h);
        } else if (j < 152) {
            int kp = j - 148;
            __half2 h = __floats2half2_rn(b1[2*kp], b1[2*kp+1]);
            val = *reinterpret_cast<uint32_t*>(&h);
        } else if (j < 156) {
            int kp = j - 152;
            __half2 h = __floats2half2_rn(w2[2*kp], w2[2*kp+1]);
            val = *reinterpret_cast<uint32_t*>(&h);
        } else {
            val = __float_as_uint(cb[0]);
        }
        swh[net][j] = val;
    }
    __syncthreads();

    int pix  = tid >> 4;         // 0..7 within block (2 pixels per warp)
    int lane = tid & 15;         // 0..15: owned depth
    int dh   = lane >> 3;        // depth-half for Phase B
    int g    = lane & 7;         // group for Phase B
    int p = blockIdx.x * 8 + pix;
    int b  = p / HWP;
    int hw = p - b * HWP;
    int h = hw / WW, w = hw - h * WW;
    float wf = (float)w, hf = (float)h;

    // ref features for group g (8 channels fp16 = one uint4)
    uint4 ru = __ldg((const uint4*)(g_refT + (size_t)p*CC) + g);
    __half2 rh0 = u2h(ru.x), rh1 = u2h(ru.y), rh2 = u2h(ru.z), rh3 = u2h(ru.w);

    // depth owned by this lane
    float myDep = __ldg(depth_sample + (size_t)b*DD*HWP + (size_t)lane*HWP + hw);

    float acc[8];
    #pragma unroll
    for (int k = 0; k < 8; k++) acc[k] = 0.f;
    float wsum = 0.f;

    for (int v = 0; v < VV; v++) {
        const float* M = g_proj + (v*BB + b)*12;
        float rx = M[0]*wf + M[1]*hf + M[2];
        float ry = M[4]*wf + M[5]*hf + M[6];
        float rz = M[8]*wf + M[9]*hf + M[10];
        float t0 = M[3], t1 = M[7], t2 = M[11];
        const __half* srcB = g_srcT + (size_t)(v*BB + b)*HWP*CC;

        // ---- Phase A: coords for owned depth ----
        {
            float px = rx*myDep + t0, py = ry*myDep + t1, pz = rz*myDep + t2;
            if (pz <= 0.001f) { px = (float)WW; py = (float)HH; pz = 1.f; }
            float ix = __fdividef(px, pz);
            float iy = __fdividef(py, pz);
            float x0f = floorf(ix), y0f = floorf(iy);
            float fx = ix - x0f, fy = iy - y0f;
            int x0 = (int)x0f, y0 = (int)y0f;
            int x1 = x0 + 1, y1 = y0 + 1;
            bool vx0 = (x0 >= 0) & (x0 < WW);
            bool vx1 = (x1 >= 0) & (x1 < WW);
            bool vy0 = (y0 >= 0) & (y0 < HH);
            bool vy1 = (y1 >= 0) & (y1 < HH);
            float w00 = (1.f-fx)*(1.f-fy) * (float)(vx0 && vy0);
            float w01 = fx*(1.f-fy)       * (float)(vx1 && vy0);
            float w10 = (1.f-fx)*fy       * (float)(vx0 && vy1);
            float w11 = fx*fy             * (float)(vx1 && vy1);
            int xc0 = min(max(x0, 0), WW-1), xc1 = min(max(x1, 0), WW-1);
            int yc0 = min(max(y0, 0), HH-1), yc1 = min(max(y1, 0), HH-1);
            int r0 = yc0*WW, r1 = yc1*WW;
            uint32_t* sc = scoord[pix][lane];
            sc[0] = (uint32_t)(r0 + xc0);
            sc[1] = (uint32_t)(r0 + xc1);
            sc[2] = (uint32_t)(r1 + xc0);
            sc[3] = (uint32_t)(r1 + xc1);
            __half2 h00 = __float2half2_rn(w00);
            __half2 h01 = __float2half2_rn(w01);
            __half2 h10 = __float2half2_rn(w10);
            __half2 h11 = __float2half2_rn(w11);
            sc[4] = *reinterpret_cast<uint32_t*>(&h00);
            sc[5] = *reinterpret_cast<uint32_t*>(&h01);
            sc[6] = *reinterpret_cast<uint32_t*>(&h10);
            sc[7] = *reinterpret_cast<uint32_t*>(&h11);
        }
        __syncwarp();

        // ---- Phase B: 8 depths per lane (lane = dh half, group g) ----
        #pragma unroll
        for (int dl = 0; dl < 8; dl++) {
            int d = dh*8 + dl;
            const uint32_t* sc = scoord[pix][d];
            uint32_t i00 = sc[0], i01 = sc[1], i10 = sc[2], i11 = sc[3];
            uint32_t c00 = sc[4], c01 = sc[5], c10 = sc[6], c11 = sc[7];
            uint4 u00 = __ldg((const uint4*)(srcB + (size_t)i00*CC) + g);
            uint4 u01 = __ldg((const uint4*)(srcB + (size_t)i01*CC) + g);
            uint4 u10 = __ldg((const uint4*)(srcB + (size_t)i10*CC) + g);
            uint4 u11 = __ldg((const uint4*)(srcB + (size_t)i11*CC) + g);
            __half2 w00 = u2h(c00), w01 = u2h(c01), w10 = u2h(c10), w11 = u2h(c11);
            __half2 m0 = __hmul2(u2h(u00.x), w00);
            __half2 m1 = __hmul2(u2h(u00.y), w00);
            __half2 m2 = __hmul2(u2h(u00.z), w00);
            __half2 m3 = __hmul2(u2h(u00.w), w00);
            m0 = __hfma2(u2h(u01.x), w01, m0);
            m1 = __hfma2(u2h(u01.y), w01, m1);
            m2 = __hfma2(u2h(u01.z), w01, m2);
            m3 = __hfma2(u2h(u01.w), w01, m3);
            m0 = __hfma2(u2h(u10.x), w10, m0);
            m1 = __hfma2(u2h(u10.y), w10, m1);
            m2 = __hfma2(u2h(u10.z), w10, m2);
            m3 = __hfma2(u2h(u10.w), w10, m3);
            m0 = __hfma2(u2h(u11.x), w11, m0);
            m1 = __hfma2(u2h(u11.y), w11, m1);
            m2 = __hfma2(u2h(u11.z), w11, m2);
            m3 = __hfma2(u2h(u11.w), w11, m3);
            __half2 da = __hmul2(m0, rh0);
            da = __hfma2(m1, rh1, da);
            da = __hfma2(m2, rh2, da);
            da = __hfma2(m3, rh3, da);
            float2 df = __half22float2(da);
            ((__half*)&simh[pix][d][0])[g] = __float2half_rn((df.x + df.y) * 0.125f);
        }
        __syncwarp();

        // ---- pixelwise net: lane owns depth = lane ----
        const uint32_t* sv = simh[pix][lane];
        float in8[8];
        {
            float2 a0 = __half22float2(u2h(sv[0]));
            float2 a1 = __half22float2(u2h(sv[1]));
            float2 a2 = __half22float2(u2h(sv[2]));
            float2 a3 = __half22float2(u2h(sv[3]));
            in8[0]=a0.x; in8[1]=a0.y; in8[2]=a1.x; in8[3]=a1.y;
            in8[4]=a2.x; in8[5]=a2.y; in8[6]=a3.x; in8[7]=a3.y;
        }
        float o = mlp8h(swh[0], in8);
        float vwv = __frcp_rn(1.f + __expf(-o));
        #pragma unroll
        for (int k = 8; k >= 1; k >>= 1)
            vwv = fmaxf(vwv, __shfl_xor_sync(0xffffffffu, vwv, k, 16));
        #pragma unroll
        for (int k = 0; k < 8; k++) acc[k] += in8[k]*vwv;
        wsum += vwv;
        if (lane == 0) out_vw[((size_t)b*VV + v)*HWP + hw] = vwv;
        __syncwarp();
    }

    float rws = 1.f / wsum;
    float in8[8];
    #pragma unroll
    for (int k = 0; k < 8; k++) in8[k] = acc[k]*rws;
    float sval = mlp8h(swh[1], in8);
    g_s[(size_t)p*DD + lane] = sval;
}

// ---------------- K3: grid-sample + NN aggregation + softmax + depth ----------------
__global__ void __launch_bounds__(128)
k_final(const float* __restrict__ grid, const float* __restrict__ weight,
        const float* __restrict__ depth_sample, const int* __restrict__ is_inverse,
        float* __restrict__ out_depth, float* __restrict__ out_score) {
    int t = blockIdx.x * blockDim.x + threadIdx.x;
    int p = t >> 2;
    int q = t & 3;
    if (p >= BB*HWP) return;
    int b  = p / HWP;
    int hw = p - b * HWP;
    int h = hw / WW, w = hw - h * WW;

    float agg[4] = {0.f, 0.f, 0.f, 0.f};

    const float* wbase = weight + ((size_t)b*DD*NV)*HWP + hw + (size_t)(q*4)*NV*HWP;
    #pragma unroll
    for (int n = 0; n < NV; n++) {
        const float* gp = grid + (((size_t)b*NV*HH + n*HH + h)*WW + w)*2;
        float gx = __ldg(gp), gy = __ldg(gp + 1);
        float ix = ((gx + 1.f)*WW - 1.f) * 0.5f;
        float iy = ((gy + 1.f)*HH - 1.f) * 0.5f;
        float x0f = floorf(ix), y0f = floorf(iy);
        float fx = ix - x0f, fy = iy - y0f;
        int x0 = (int)x0f, y0 = (int)y0f;
        int xc0 = min(max(x0, 0), WW-1), xc1 = min(max(x0+1, 0), WW-1);
        int yc0 = min(max(y0, 0), HH-1), yc1 = min(max(y0+1, 0), HH-1);
        float w00 = (1.f-fx)*(1.f-fy), w01 = fx*(1.f-fy);
        float w10 = (1.f-fx)*fy,       w11 = fx*fy;
        float4 a00 = __ldg((const float4*)(g_s + ((size_t)b*HWP + yc0*WW + xc0)*DD) + q);
        float4 a01 = __ldg((const float4*)(g_s + ((size_t)b*HWP + yc0*WW + xc1)*DD) + q);
        float4 a10 = __ldg((const float4*)(g_s + ((size_t)b*HWP + yc1*WW + xc0)*DD) + q);
        float4 a11 = __ldg((const float4*)(g_s + ((size_t)b*HWP + yc1*WW + xc1)*DD) + q);
        float bx = w00*a00.x + w01*a01.x + w10*a10.x + w11*a11.x;
        float by = w00*a00.y + w01*a01.y + w10*a10.y + w11*a11.y;
        float bz = w00*a00.z + w01*a01.z + w10*a10.z + w11*a11.z;
        float bw = w00*a00.w + w01*a01.w + w10*a10.w + w11*a11.w;
        const float* wb = wbase + (size_t)n*HWP;
        agg[0] += __ldg(wb)                      * bx;
        agg[1] += __ldg(wb + (size_t)1*NV*HWP)   * by;
        agg[2] += __ldg(wb + (size_t)2*NV*HWP)   * bz;
        agg[3] += __ldg(wb + (size_t)3*NV*HWP)   * bw;
    }

    float m = fmaxf(fmaxf(agg[0], agg[1]), fmaxf(agg[2], agg[3]));
    m = fmaxf(m, __shfl_xor_sync(0xffffffffu, m, 1, 4));
    m = fmaxf(m, __shfl_xor_sync(0xffffffffu, m, 2, 4));
    float e[4]; float sum = 0.f;
    #pragma unroll
    for (int j = 0; j < 4; j++) { e[j] = __expf(agg[j] - m); sum += e[j]; }
    sum += __shfl_xor_sync(0xffffffffu, sum, 1, 4);
    sum += __shfl_xor_sync(0xffffffffu, sum, 2, 4);
    float rs = 1.f / sum;

    const float* dsB = depth_sample + (size_t)b*DD*HWP + hw;
    float dep = 0.f;
    int inv = *is_inverse;
    #pragma unroll
    for (int j = 0; j < 4; j++) {
        float sc = e[j] * rs;
        int d = q*4 + j;
        out_score[((size_t)b*DD + d)*HWP + hw] = sc;
        if (inv) dep += (float)d * sc;
        else     dep += __ldg(dsB + (size_t)d*HWP) * sc;
    }
    dep += __shfl_xor_sync(0xffffffffu, dep, 1, 4);
    dep += __shfl_xor_sync(0xffffffffu, dep, 2, 4);
    if (q == 0) {
        if (inv) {
            float invmin = 1.f / __ldg(dsB + (size_t)(DD-1)*HWP);
            float invmax = 1.f / __ldg(dsB);
            dep = 1.f / (invmax + dep * (1.f/(float)(DD-1)) * (invmin - invmax));
        }
        out_depth[p] = dep;
    }
}

// ---------------- launch ----------------
extern "C" void kernel_launch(void* const* d_in, const int* in_sizes, int n_in,
                              void* d_out, int out_size) {
    const float* ref_feature  = (const float*)d_in[0];
    const float* src_features = (const float*)d_in[1];
    const float* ref_proj     = (const float*)d_in[2];
    const float* src_projs    = (const float*)d_in[3];
    const float* depth_sample = (const float*)d_in[4];
    const float* grid         = (const float*)d_in[5];
    const float* weight       = (const float*)d_in[6];
    const float* pw_w0  = (const float*)d_in[7];
    const float* pw_g0  = (const float*)d_in[8];
    const float* pw_b0  = (const float*)d_in[9];
    const float* pw_w1  = (const float*)d_in[10];
    const float* pw_g1  = (const float*)d_in[11];
    const float* pw_b1  = (const float*)d_in[12];
    const float* pw_w2  = (const float*)d_in[13];
    const float* pw_c2b = (const float*)d_in[14];
    const float* sn_w0  = (const float*)d_in[15];
    const float* sn_g0  = (const float*)d_in[16];
    const float* sn_b0  = (const float*)d_in[17];
    const float* sn_w1  = (const float*)d_in[18];
    const float* sn_g1  = (const float*)d_in[19];
    const float* sn_b1  = (const float*)d_in[20];
    const float* sn_w2  = (const float*)d_in[21];
    const float* sn_c2b = (const float*)d_in[22];
    const int*   is_inv = (const int*)d_in[23];

    float* out       = (float*)d_out;
    float* out_depth = out;
    float* out_score = out + (size_t)BB*HWP;
    float* out_vw    = out + (size_t)BB*HWP + (size_t)BB*DD*HWP;

    k_transpose<<<dim3(HWP/64, VV*BB + BB), 256>>>(ref_feature, src_features);
    k_proj<<<1, 32>>>(ref_proj, src_projs);
    k_main<<<BB*HWP/8, 128>>>(depth_sample,
                              pw_w0, pw_g0, pw_b0, pw_w1, pw_g1, pw_b1, pw_w2, pw_c2b,
                              sn_w0, sn_g0, sn_b0, sn_w1, sn_g1, sn_b1, sn_w2, sn_c2b,
                              out_vw);
    k_final<<<(BB*HWP*4 + 127)/128, 128>>>(grid, weight, depth_sample, is_inv,
                                           out_depth, out_score);
}

// round 8
// speedup vs baseline: 1.1233x; 1.0166x over previous
#include <cuda_runtime.h>
#include <cuda_fp16.h>
#include <math.h>
#include <stdint.h>

#define BB 2
#define CC 64
#define HH 128
#define WW 160
#define DD 16
#define VV 4
#define NV 9
#define HWP (HH*WW)

// ---------------- scratch (static device memory; no allocation) ----------------
__device__ __align__(16) __half g_srcT[(size_t)VV*BB*HWP*CC]; // fp16 [v*B+b][hw][c]
__device__ __align__(16) __half g_refT[(size_t)BB*HWP*CC];    // fp16 [b][hw][c]
__device__ float g_proj[VV*BB*12];
__device__ __align__(16) float g_s[(size_t)BB*HWP*DD];        // s channels-last [b][hw][d]

#define BNS 0.9999950000374997f

// ---------------- K0: transpose [C,HW] -> [HW,C]; all -> fp16 ----------------
__global__ void k_transpose(const float* __restrict__ ref, const float* __restrict__ src) {
    __shared__ float tile[64][65];
    int img = blockIdx.y;          // 0..7 = src v*B+b, 8..9 = ref b
    int hw0 = blockIdx.x * 64;
    const float* in = (img < VV*BB) ? (src + (size_t)img*CC*HWP)
                                    : (ref + (size_t)(img - VV*BB)*CC*HWP);
    for (int k = threadIdx.x; k < 64*64; k += blockDim.x) {
        int c = k >> 6, hwl = k & 63;
        tile[hwl][c] = in[(size_t)c*HWP + hw0 + hwl];
    }
    __syncthreads();
    __half2* out = (img < VV*BB)
        ? (__half2*)(g_srcT + (size_t)img*HWP*CC)
        : (__half2*)(g_refT + (size_t)(img - VV*BB)*HWP*CC);
    for (int k = threadIdx.x; k < 64*32; k += blockDim.x) {
        int hwl = k >> 5, cp = k & 31;
        out[(size_t)(hw0+hwl)*(CC/2) + cp] =
            __floats2half2_rn(tile[hwl][2*cp], tile[hwl][2*cp+1]);
    }
}

// ---------------- K1: proj = src_proj @ inv(ref_proj) ----------------
__global__ void k_proj(const float* __restrict__ ref_proj, const float* __restrict__ src_projs) {
    int t = threadIdx.x;
    if (t >= VV*BB) return;
    int v = t / BB, b = t % BB;
    float a[4][4], inv[4][4];
    #pragma unroll
    for (int i = 0; i < 4; i++)
        #pragma unroll
        for (int j = 0; j < 4; j++) {
            a[i][j] = ref_proj[b*16 + i*4 + j];
            inv[i][j] = (i == j) ? 1.f : 0.f;
        }
    for (int col = 0; col < 4; col++) {
        int piv = col; float best = fabsf(a[col][col]);
        for (int r = col+1; r < 4; r++) { float av = fabsf(a[r][col]); if (av > best) { best = av; piv = r; } }
        if (piv != col) {
            for (int j = 0; j < 4; j++) {
                float tm = a[col][j]; a[col][j] = a[piv][j]; a[piv][j] = tm;
                tm = inv[col][j]; inv[col][j] = inv[piv][j]; inv[piv][j] = tm;
            }
        }
        float dsc = 1.f / a[col][col];
        for (int j = 0; j < 4; j++) { a[col][j] *= dsc; inv[col][j] *= dsc; }
        for (int r = 0; r < 4; r++) {
            if (r == col) continue;
            float f = a[r][col];
            for (int j = 0; j < 4; j++) { a[r][j] -= f*a[col][j]; inv[r][j] -= f*inv[col][j]; }
        }
    }
    const float* s = src_projs + (size_t)(v*BB + b)*16;
    float* o = g_proj + (v*BB + b)*12;
    for (int i = 0; i < 3; i++)
        for (int j = 0; j < 4; j++) {
            float acc = 0.f;
            for (int k = 0; k < 4; k++) acc += s[i*4 + k] * inv[k][j];
            o[i*4 + j] = acc;
        }
}

// ---------------- fp16 packed MLP (8 -> 16 -> 8 -> 1) ----------------
__device__ __forceinline__ __half2 u2h(uint32_t u) { return *reinterpret_cast<__half2*>(&u); }

__device__ __forceinline__ float mlp8h(const uint32_t* __restrict__ swh, const float in8[8]) {
    __half2 ind[8];
    #pragma unroll
    for (int g = 0; g < 8; g++) ind[g] = __float2half2_rn(in8[g]);
    const uint4* W0 = (const uint4*)swh;
    const uint4* W1 = (const uint4*)(swh + 80);
    const __half2 zero = __float2half2_rn(0.f);
    __half2 h1[8];
    #pragma unroll
    for (int jp = 0; jp < 8; jp++) {
        uint4 wa = W0[jp*2], wb = W0[jp*2+1];
        __half2 acc = __hmul2(u2h(wa.x), ind[0]);
        acc = __hfma2(u2h(wa.y), ind[1], acc);
        acc = __hfma2(u2h(wa.z), ind[2], acc);
        acc = __hfma2(u2h(wa.w), ind[3], acc);
        acc = __hfma2(u2h(wb.x), ind[4], acc);
        acc = __hfma2(u2h(wb.y), ind[5], acc);
        acc = __hfma2(u2h(wb.z), ind[6], acc);
        acc = __hfma2(u2h(wb.w), ind[7], acc);
        acc = __hfma2(acc, u2h(swh[64 + jp]), u2h(swh[72 + jp]));
        h1[jp] = __hmax2(acc, zero);
    }
    __half2 hd[16];
    #pragma unroll
    for (int jp = 0; jp < 8; jp++) {
        hd[2*jp]   = __low2half2(h1[jp]);
        hd[2*jp+1] = __high2half2(h1[jp]);
    }
    __half2 oacc = zero;
    #pragma unroll
    for (int kp = 0; kp < 4; kp++) {
        uint4 w0v = W1[kp*4], w1v = W1[kp*4+1], w2v = W1[kp*4+2], w3v = W1[kp*4+3];
        __half2 acc = __hmul2(u2h(w0v.x), hd[0]);
        acc = __hfma2(u2h(w0v.y), hd[1], acc);
        acc = __hfma2(u2h(w0v.z), hd[2], acc);
        acc = __hfma2(u2h(w0v.w), hd[3], acc);
        acc = __hfma2(u2h(w1v.x), hd[4], acc);
        acc = __hfma2(u2h(w1v.y), hd[5], acc);
        acc = __hfma2(u2h(w1v.z), hd[6], acc);
        acc = __hfma2(u2h(w1v.w), hd[7], acc);
        acc = __hfma2(u2h(w2v.x), hd[8], acc);
        acc = __hfma2(u2h(w2v.y), hd[9], acc);
        acc = __hfma2(u2h(w2v.z), hd[10], acc);
        acc = __hfma2(u2h(w2v.w), hd[11], acc);
        acc = __hfma2(u2h(w3v.x), hd[12], acc);
        acc = __hfma2(u2h(w3v.y), hd[13], acc);
        acc = __hfma2(u2h(w3v.z), hd[14], acc);
        acc = __hfma2(u2h(w3v.w), hd[15], acc);
        acc = __hfma2(acc, u2h(swh[144 + kp]), u2h(swh[148 + kp]));
        acc = __hmax2(acc, zero);
        oacc = __hfma2(u2h(swh[152 + kp]), acc, oacc);
    }
    float2 of = __half22float2(oacc);
    return of.x + of.y + __uint_as_float(swh[156]);
}

// ---------------- K2: warp + group correlation + pixelwise net + similarity net ----------------
// block = 128 threads = 8 pixels × 16 lanes; lane = (dh, g).
// scoord packed: 4 words/depth = (i00|i01<<16, i10|i11<<16, h2(w00,w01), h2(w10,w11)), stride 6.
__global__ void __launch_bounds__(128)
k_main(const float* __restrict__ depth_sample,
       const float* __restrict__ pw_w0, const float* __restrict__ pw_g0, const float* __restrict__ pw_b0,
       const float* __restrict__ pw_w1, const float* __restrict__ pw_g1, const float* __restrict__ pw_b1,
       const float* __restrict__ pw_w2, const float* __restrict__ pw_c2b,
       const float* __restrict__ sn_w0, const float* __restrict__ sn_g0, const float* __restrict__ sn_b0,
       const float* __restrict__ sn_w1, const float* __restrict__ sn_g1, const float* __restrict__ sn_b1,
       const float* __restrict__ sn_w2, const float* __restrict__ sn_c2b,
       float* __restrict__ out_vw) {
    __shared__ __align__(16) uint32_t swh[2][160];
    __shared__ __align__(16) uint32_t scoord[8][16][6]; // packed coords, stride 6 words
    __shared__ uint32_t simh [8][16][5];  // [pix][d][4 half2 + pad]; stride 5 (coprime w/ 32)

    int tid = threadIdx.x;

    // pack fp16 MLP weights
    for (int i = tid; i < 320; i += 128) {
        int net = i / 160, j = i - net*160;
        const float* w0 = net ? sn_w0 : pw_w0;
        const float* g0 = net ? sn_g0 : pw_g0;
        const float* b0 = net ? sn_b0 : pw_b0;
        const float* w1 = net ? sn_w1 : pw_w1;
        const float* g1 = net ? sn_g1 : pw_g1;
        const float* b1 = net ? sn_b1 : pw_b1;
        const float* w2 = net ? sn_w2 : pw_w2;
        const float* cb = net ? sn_c2b : pw_c2b;
        uint32_t val;
        if (j < 64) {
            int jp = j >> 3, g = j & 7;
            __half2 h = __floats2half2_rn(w0[(2*jp)*8 + g], w0[(2*jp+1)*8 + g]);
            val = *reinterpret_cast<uint32_t*>(&h);
        } else if (j < 72) {
            int jp = j - 64;
            __half2 h = __floats2half2_rn(g0[2*jp]*BNS, g0[2*jp+1]*BNS);
            val = *reinterpret_cast<uint32_t*>(&h);
        } else if (j < 80) {
            int jp = j - 72;
            __half2 h = __floats2half2_rn(b0[2*jp], b0[2*jp+1]);
            val = *reinterpret_cast<uint32_t*>(&h);
        } else if (j < 144) {
            int idx = j - 80; int kp = idx >> 4, jj = idx & 15;
            __half2 h = __floats2half2_rn(w1[(2*kp)*16 + jj], w1[(2*kp+1)*16 + jj]);
            val = *reinterpret_cast<uint32_t*>(&h);
        } else if (j < 148) {
            int kp = j - 144;
            __half2 h = __floats2half2_rn(g1[2*kp]*BNS, g1[2*kp+1]*BNS);
            val = *reinterpret_cast<uint32_t*>(&h);
        } else if (j < 152) {
            int kp = j - 148;
            __half2 h = __floats2half2_rn(b1[2*kp], b1[2*kp+1]);
            val = *reinterpret_cast<uint32_t*>(&h);
        } else if (j < 156) {
            int kp = j - 152;
            __half2 h = __floats2half2_rn(w2[2*kp], w2[2*kp+1]);
            val = *reinterpret_cast<uint32_t*>(&h);
        } else {
            val = __float_as_uint(cb[0]);
        }
        swh[net][j] = val;
    }
    __syncthreads();

    int pix  = tid >> 4;         // 0..7 within block (2 pixels per warp)
    int lane = tid & 15;         // 0..15: owned depth
    int dh   = lane >> 3;        // depth-half for Phase B
    int g    = lane & 7;         // group for Phase B
    int p = blockIdx.x * 8 + pix;
    int b  = p / HWP;
    int hw = p - b * HWP;
    int h = hw / WW, w = hw - h * WW;
    float wf = (float)w, hf = (float)h;

    // ref features for group g (8 channels fp16 = one uint4)
    uint4 ru = __ldg((const uint4*)(g_refT + (size_t)p*CC) + g);
    __half2 rh0 = u2h(ru.x), rh1 = u2h(ru.y), rh2 = u2h(ru.z), rh3 = u2h(ru.w);

    // depth owned by this lane
    float myDep = __ldg(depth_sample + (size_t)b*DD*HWP + (size_t)lane*HWP + hw);

    float acc[8];
    #pragma unroll
    for (int k = 0; k < 8; k++) acc[k] = 0.f;
    float wsum = 0.f;

    for (int v = 0; v < VV; v++) {
        const float* M = g_proj + (v*BB + b)*12;
        float rx = M[0]*wf + M[1]*hf + M[2];
        float ry = M[4]*wf + M[5]*hf + M[6];
        float rz = M[8]*wf + M[9]*hf + M[10];
        float t0 = M[3], t1 = M[7], t2 = M[11];
        const __half* srcB = g_srcT + (size_t)(v*BB + b)*HWP*CC;

        // ---- Phase A: coords for owned depth (packed to 4 words) ----
        {
            float px = rx*myDep + t0, py = ry*myDep + t1, pz = rz*myDep + t2;
            if (pz <= 0.001f) { px = (float)WW; py = (float)HH; pz = 1.f; }
            float ix = __fdividef(px, pz);
            float iy = __fdividef(py, pz);
            float x0f = floorf(ix), y0f = floorf(iy);
            float fx = ix - x0f, fy = iy - y0f;
            int x0 = (int)x0f, y0 = (int)y0f;
            int x1 = x0 + 1, y1 = y0 + 1;
            bool vx0 = (x0 >= 0) & (x0 < WW);
            bool vx1 = (x1 >= 0) & (x1 < WW);
            bool vy0 = (y0 >= 0) & (y0 < HH);
            bool vy1 = (y1 >= 0) & (y1 < HH);
            float w00 = (1.f-fx)*(1.f-fy) * (float)(vx0 && vy0);
            float w01 = fx*(1.f-fy)       * (float)(vx1 && vy0);
            float w10 = (1.f-fx)*fy       * (float)(vx0 && vy1);
            float w11 = fx*fy             * (float)(vx1 && vy1);
            int xc0 = min(max(x0, 0), WW-1), xc1 = min(max(x1, 0), WW-1);
            int yc0 = min(max(y0, 0), HH-1), yc1 = min(max(y1, 0), HH-1);
            int r0 = yc0*WW, r1 = yc1*WW;
            uint32_t i00 = (uint32_t)(r0 + xc0), i01 = (uint32_t)(r0 + xc1);
            uint32_t i10 = (uint32_t)(r1 + xc0), i11 = (uint32_t)(r1 + xc1);
            __half2 hw01 = __floats2half2_rn(w00, w01);
            __half2 hw23 = __floats2half2_rn(w10, w11);
            uint32_t* sc = scoord[pix][lane];
            *(uint2*)&sc[0] = make_uint2(i00 | (i01 << 16), i10 | (i11 << 16));
            *(uint2*)&sc[2] = make_uint2(*reinterpret_cast<uint32_t*>(&hw01),
                                         *reinterpret_cast<uint32_t*>(&hw23));
        }
        __syncwarp();

        // ---- Phase B: 8 depths per lane (lane = dh half, group g) ----
        #pragma unroll
        for (int dl = 0; dl < 8; dl++) {
            int d = dh*8 + dl;
            uint2 ia = *(const uint2*)&scoord[pix][d][0];
            uint2 wv = *(const uint2*)&scoord[pix][d][2];
            uint32_t i00 = ia.x & 0xFFFFu, i01 = ia.x >> 16;
            uint32_t i10 = ia.y & 0xFFFFu, i11 = ia.y >> 16;
            __half2 pw01 = u2h(wv.x), pw23 = u2h(wv.y);
            __half2 w00 = __low2half2(pw01),  w01 = __high2half2(pw01);
            __half2 w10 = __low2half2(pw23),  w11 = __high2half2(pw23);
            uint4 u00 = __ldg((const uint4*)(srcB + (size_t)i00*CC) + g);
            uint4 u01 = __ldg((const uint4*)(srcB + (size_t)i01*CC) + g);
            uint4 u10 = __ldg((const uint4*)(srcB + (size_t)i10*CC) + g);
            uint4 u11 = __ldg((const uint4*)(srcB + (size_t)i11*CC) + g);
            __half2 m0 = __hmul2(u2h(u00.x), w00);
            __half2 m1 = __hmul2(u2h(u00.y), w00);
            __half2 m2 = __hmul2(u2h(u00.z), w00);
            __half2 m3 = __hmul2(u2h(u00.w), w00);
            m0 = __hfma2(u2h(u01.x), w01, m0);
            m1 = __hfma2(u2h(u01.y), w01, m1);
            m2 = __hfma2(u2h(u01.z), w01, m2);
            m3 = __hfma2(u2h(u01.w), w01, m3);
            m0 = __hfma2(u2h(u10.x), w10, m0);
            m1 = __hfma2(u2h(u10.y), w10, m1);
            m2 = __hfma2(u2h(u10.z), w10, m2);
            m3 = __hfma2(u2h(u10.w), w10, m3);
            m0 = __hfma2(u2h(u11.x), w11, m0);
            m1 = __hfma2(u2h(u11.y), w11, m1);
            m2 = __hfma2(u2h(u11.z), w11, m2);
            m3 = __hfma2(u2h(u11.w), w11, m3);
            __half2 da = __hmul2(m0, rh0);
            da = __hfma2(m1, rh1, da);
            da = __hfma2(m2, rh2, da);
            da = __hfma2(m3, rh3, da);
            float2 df = __half22float2(da);
            ((__half*)&simh[pix][d][0])[g] = __float2half_rn((df.x + df.y) * 0.125f);
        }
        __syncwarp();

        // ---- pixelwise net: lane owns depth = lane ----
        const uint32_t* sv = simh[pix][lane];
        float in8[8];
        {
            float2 a0 = __half22float2(u2h(sv[0]));
            float2 a1 = __half22float2(u2h(sv[1]));
            float2 a2 = __half22float2(u2h(sv[2]));
            float2 a3 = __half22float2(u2h(sv[3]));
            in8[0]=a0.x; in8[1]=a0.y; in8[2]=a1.x; in8[3]=a1.y;
            in8[4]=a2.x; in8[5]=a2.y; in8[6]=a3.x; in8[7]=a3.y;
        }
        float o = mlp8h(swh[0], in8);
        float vwv = __frcp_rn(1.f + __expf(-o));
        #pragma unroll
        for (int k = 8; k >= 1; k >>= 1)
            vwv = fmaxf(vwv, __shfl_xor_sync(0xffffffffu, vwv, k, 16));
        #pragma unroll
        for (int k = 0; k < 8; k++) acc[k] += in8[k]*vwv;
        wsum += vwv;
        if (lane == 0) out_vw[((size_t)b*VV + v)*HWP + hw] = vwv;
        __syncwarp();
    }

    float rws = 1.f / wsum;
    float in8[8];
    #pragma unroll
    for (int k = 0; k < 8; k++) in8[k] = acc[k]*rws;
    float sval = mlp8h(swh[1], in8);
    g_s[(size_t)p*DD + lane] = sval;
}

// ---------------- K3: grid-sample + NN aggregation + softmax + depth ----------------
__global__ void __launch_bounds__(128)
k_final(const float* __restrict__ grid, const float* __restrict__ weight,
        const float* __restrict__ depth_sample, const int* __restrict__ is_inverse,
        float* __restrict__ out_depth, float* __restrict__ out_score) {
    int t = blockIdx.x * blockDim.x + threadIdx.x;
    int p = t >> 2;
    int q = t & 3;
    if (p >= BB*HWP) return;
    int b  = p / HWP;
    int hw = p - b * HWP;
    int h = hw / WW, w = hw - h * WW;

    float agg[4] = {0.f, 0.f, 0.f, 0.f};

    const float* wbase = weight + ((size_t)b*DD*NV)*HWP + hw + (size_t)(q*4)*NV*HWP;
    #pragma unroll
    for (int n = 0; n < NV; n++) {
        const float* gp = grid + (((size_t)b*NV*HH + n*HH + h)*WW + w)*2;
        float gx = __ldg(gp), gy = __ldg(gp + 1);
        float ix = ((gx + 1.f)*WW - 1.f) * 0.5f;
        float iy = ((gy + 1.f)*HH - 1.f) * 0.5f;
        float x0f = floorf(ix), y0f = floorf(iy);
        float fx = ix - x0f, fy = iy - y0f;
        int x0 = (int)x0f, y0 = (int)y0f;
        int xc0 = min(max(x0, 0), WW-1), xc1 = min(max(x0+1, 0), WW-1);
        int yc0 = min(max(y0, 0), HH-1), yc1 = min(max(y0+1, 0), HH-1);
        float w00 = (1.f-fx)*(1.f-fy), w01 = fx*(1.f-fy);
        float w10 = (1.f-fx)*fy,       w11 = fx*fy;
        float4 a00 = __ldg((const float4*)(g_s + ((size_t)b*HWP + yc0*WW + xc0)*DD) + q);
        float4 a01 = __ldg((const float4*)(g_s + ((size_t)b*HWP + yc0*WW + xc1)*DD) + q);
        float4 a10 = __ldg((const float4*)(g_s + ((size_t)b*HWP + yc1*WW + xc0)*DD) + q);
        float4 a11 = __ldg((const float4*)(g_s + ((size_t)b*HWP + yc1*WW + xc1)*DD) + q);
        float bx = w00*a00.x + w01*a01.x + w10*a10.x + w11*a11.x;
        float by = w00*a00.y + w01*a01.y + w10*a10.y + w11*a11.y;
        float bz = w00*a00.z + w01*a01.z + w10*a10.z + w11*a11.z;
        float bw = w00*a00.w + w01*a01.w + w10*a10.w + w11*a11.w;
        const float* wb = wbase + (size_t)n*HWP;
        agg[0] += __ldg(wb)                      * bx;
        agg[1] += __ldg(wb + (size_t)1*NV*HWP)   * by;
        agg[2] += __ldg(wb + (size_t)2*NV*HWP)   * bz;
        agg[3] += __ldg(wb + (size_t)3*NV*HWP)   * bw;
    }

    float m = fmaxf(fmaxf(agg[0], agg[1]), fmaxf(agg[2], agg[3]));
    m = fmaxf(m, __shfl_xor_sync(0xffffffffu, m, 1, 4));
    m = fmaxf(m, __shfl_xor_sync(0xffffffffu, m, 2, 4));
    float e[4]; float sum = 0.f;
    #pragma unroll
    for (int j = 0; j < 4; j++) { e[j] = __expf(agg[j] - m); sum += e[j]; }
    sum += __shfl_xor_sync(0xffffffffu, sum, 1, 4);
    sum += __shfl_xor_sync(0xffffffffu, sum, 2, 4);
    float rs = 1.f / sum;

    const float* dsB = depth_sample + (size_t)b*DD*HWP + hw;
    float dep = 0.f;
    int inv = *is_inverse;
    #pragma unroll
    for (int j = 0; j < 4; j++) {
        float sc = e[j] * rs;
        int d = q*4 + j;
        out_score[((size_t)b*DD + d)*HWP + hw] = sc;
        if (inv) dep += (float)d * sc;
        else     dep += __ldg(dsB + (size_t)d*HWP) * sc;
    }
    dep += __shfl_xor_sync(0xffffffffu, dep, 1, 4);
    dep += __shfl_xor_sync(0xffffffffu, dep, 2, 4);
    if (q == 0) {
        if (inv) {
            float invmin = 1.f / __ldg(dsB + (size_t)(DD-1)*HWP);
            float invmax = 1.f / __ldg(dsB);
            dep = 1.f / (invmax + dep * (1.f/(float)(DD-1)) * (invmin - invmax));
        }
        out_depth[p] = dep;
    }
}

// ---------------- launch ----------------
extern "C" void kernel_launch(void* const* d_in, const int* in_sizes, int n_in,
                              void* d_out, int out_size) {
    const float* ref_feature  = (const float*)d_in[0];
    const float* src_features = (const float*)d_in[1];
    const float* ref_proj     = (const float*)d_in[2];
    const float* src_projs    = (const float*)d_in[3];
    const float* depth_sample = (const float*)d_in[4];
    const float* grid         = (const float*)d_in[5];
    const float* weight       = (const float*)d_in[6];
    const float* pw_w0  = (const float*)d_in[7];
    const float* pw_g0  = (const float*)d_in[8];
    const float* pw_b0  = (const float*)d_in[9];
    const float* pw_w1  = (const float*)d_in[10];
    const float* pw_g1  = (const float*)d_in[11];
    const float* pw_b1  = (const float*)d_in[12];
    const float* pw_w2  = (const float*)d_in[13];
    const float* pw_c2b = (const float*)d_in[14];
    const float* sn_w0  = (const float*)d_in[15];
    const float* sn_g0  = (const float*)d_in[16];
    const float* sn_b0  = (const float*)d_in[17];
    const float* sn_w1  = (const float*)d_in[18];
    const float* sn_g1  = (const float*)d_in[19];
    const float* sn_b1  = (const float*)d_in[20];
    const float* sn_w2  = (const float*)d_in[21];
    const float* sn_c2b = (const float*)d_in[22];
    const int*   is_inv = (const int*)d_in[23];

    float* out       = (float*)d_out;
    float* out_depth = out;
    float* out_score = out + (size_t)BB*HWP;
    float* out_vw    = out + (size_t)BB*HWP + (size_t)BB*DD*HWP;

    k_transpose<<<dim3(HWP/64, VV*BB + BB), 256>>>(ref_feature, src_features);
    k_proj<<<1, 32>>>(ref_proj, src_projs);
    k_main<<<BB*HWP/8, 128>>>(depth_sample,
                              pw_w0, pw_g0, pw_b0, pw_w1, pw_g1, pw_b1, pw_w2, pw_c2b,
                              sn_w0, sn_g0, sn_b0, sn_w1, sn_g1, sn_b1, sn_w2, sn_c2b,
                              out_vw);
    k_final<<<(BB*HWP*4 + 127)/128, 128>>>(grid, weight, depth_sample, is_inv,
                                           out_depth, out_score);
}